// round 13
// baseline (speedup 1.0000x reference)
#include <cuda_runtime.h>
#include <cstdint>

#define Bq 8192
#define Nn 524288
#define Hh 256
#define KDd 128
#define VDd 128
#define SCALE 0.08838834764831845f  /* 1/sqrt(128) */

// ---------------- scratch (device globals; no allocation allowed) -----------
__device__ __align__(16) float g_rs[Bq * Hh];
__device__ __align__(16) float g_u[Bq * Hh];
__device__ __align__(16) float g_denom[Bq];
__device__ __align__(16) float g_AT[KDd * Hh];    // [128][256]
__device__ __align__(16) float g_a0[Hh];
__device__ __align__(16) float g_Mt[Hh * VDd];    // [256][128]
__device__ __align__(16) float g_d[VDd];

// ---------------- merged prep (standalone; R9-proven) --------------------------
__global__ void prep_all(const float* __restrict__ Wq, const float* __restrict__ bq,
                         const float* __restrict__ Wk, const float* __restrict__ bk,
                         const float* __restrict__ Wv, const float* __restrict__ bv,
                         const float* __restrict__ Wo, const float* __restrict__ bo) {
    __shared__ float col[Hh];
    int blk = blockIdx.x;
    int t = threadIdx.x;  // 256 threads
    if (blk < KDd + 1) {
        int bi = blk;
        if (t < KDd) col[t] = (bi < KDd) ? Wq[t * KDd + bi] : bq[t];
        __syncthreads();
        float s = 0.0f;
        #pragma unroll 8
        for (int r = 0; r < KDd; ++r) s += Wk[r * Hh + t] * col[r];
        if (bi < KDd) g_AT[bi * Hh + t] = s * SCALE;
        else          g_a0[t] = s * SCALE;
    } else {
        int j = blk - (KDd + 1);   // 0..256
        if (t < VDd) col[t] = (j < Hh) ? Wv[t * Hh + j] : bv[t];
        __syncthreads();
        if (t < VDd) {
            float acc = 0.0f;
            const float4* wrow = (const float4*)(Wo + t * VDd);
            #pragma unroll 8
            for (int o4 = 0; o4 < VDd / 4; ++o4) {
                float4 w = wrow[o4];
                int o = o4 * 4;
                acc += w.x * col[o] + w.y * col[o + 1] + w.z * col[o + 2] + w.w * col[o + 3];
            }
            if (j < Hh) g_Mt[j * VDd + t] = acc;
            else        g_d[t] = acc + bo[t];
        }
    }
}

// ---------------- tf32 / cp.async helpers --------------------------------------
__device__ __forceinline__ uint32_t f2tf32(float x) {
    uint32_t r;
    asm("cvt.rna.tf32.f32 %0, %1;" : "=r"(r) : "f"(x));
    return r;
}

__device__ __forceinline__ void mma_tf32(float* c, const uint32_t* a, uint32_t b0, uint32_t b1) {
    asm volatile(
        "mma.sync.aligned.m16n8k8.row.col.f32.tf32.tf32.f32 "
        "{%0,%1,%2,%3}, {%4,%5,%6,%7}, {%8,%9}, {%0,%1,%2,%3};"
        : "+f"(c[0]), "+f"(c[1]), "+f"(c[2]), "+f"(c[3])
        : "r"(a[0]), "r"(a[1]), "r"(a[2]), "r"(a[3]), "r"(b0), "r"(b1));
}

__device__ __forceinline__ void cp_async16(uint32_t smem_dst, const void* gmem_src) {
    asm volatile("cp.async.cg.shared.global [%0], [%1], 16;\n" :: "r"(smem_dst), "l"(gmem_src));
}
__device__ __forceinline__ void cp_commit() {
    asm volatile("cp.async.commit_group;\n" ::: "memory");
}
template <int N>
__device__ __forceinline__ void cp_wait() {
    asm volatile("cp.async.wait_group %0;\n" :: "n"(N) : "memory");
}

// ---------------- tf32 GEMM: 3-stage cp.async pipeline, chunk 32, BN=32 --------
// 256 threads (8 warps: 2m x 4n), warp tile m32 x n8, BM=64.
// Pipeline (CUTLASS order): iter c -> wait_group(1) [chunk c arrived],
// __syncthreads [visibility + frees buf (c-1)%3], issue chunk c+2 into that
// buffer via cp.async (no registers, ptxas cannot collapse it), compute chunk c.
// 2 chunk-times of DRAM latency cover.
// MODE 0: g_rs = query @ g_AT + g_a0    K=128, NC=4, grid (8,128)=1024. + zero g_u.
// MODE 1: out = (g_u/den) @ g_Mt + g_d  K=256, NC=8, grid (4,128)=512.
template <int MODE>
__global__ __launch_bounds__(256) void gemm_tc(const float* __restrict__ Xext,
                                               float* __restrict__ Cext,
                                               const float* __restrict__ boext) {
    constexpr int K = (MODE == 0) ? KDd : Hh;
    constexpr int NOUT = (MODE == 0) ? Hh : VDd;
    constexpr int NC = K / 32;
    const float* X = (MODE == 0) ? Xext : g_u;
    const float* W = (MODE == 0) ? g_AT : g_Mt;
    const float* bias = (MODE == 0) ? g_a0 : g_d;

    const int tid = threadIdx.x;
    const int warp = tid >> 5;
    const int lane = tid & 31;
    const int wm = warp & 1;            // m position (32-row strip)
    const int wn = warp >> 1;           // n position (8-col strip), 0..3

    if (MODE == 0) {
        // fold g_u/g_denom zero-init (1024 blocks cover all of g_u)
        int bid = blockIdx.y * gridDim.x + blockIdx.x;  // 0..1023
        float4 z = make_float4(0.f, 0.f, 0.f, 0.f);
        float4* u4 = (float4*)g_u;
        u4[(size_t)bid * 512 + tid] = z;
        u4[(size_t)bid * 512 + 256 + tid] = z;
        if (tid < 8) g_denom[bid * 8 + tid] = 0.0f;
    }

    __shared__ float Xs[3][64][36];    // raw fp32 X; stride 36: conflict-free A-frags
    __shared__ float Ws[3][32][40];    // raw fp32 W; stride 40: conflict-free B-frags (8k+b)

    const int m0 = blockIdx.y * 64;
    const int n0 = blockIdx.x * 32;

    // cooperative-load indices: X tile 64x32 (2 x 16B/thread), W tile 32x32 (1 x 16B/thread)
    const int xr = tid >> 2;
    const int xc = (tid & 3) << 3;
    const int wr = tid >> 3;
    const int wc = (tid & 7) << 2;

    const float* xbase = X + (size_t)(m0 + xr) * K + xc;
    const float* wbase = W + (size_t)wr * NOUT + n0 + wc;

    // ---- prologue: issue chunks 0 and 1 as separate commit groups
    {
        cp_async16((uint32_t)__cvta_generic_to_shared(&Xs[0][xr][xc]), xbase);
        cp_async16((uint32_t)__cvta_generic_to_shared(&Xs[0][xr][xc + 4]), xbase + 4);
        cp_async16((uint32_t)__cvta_generic_to_shared(&Ws[0][wr][wc]), wbase);
        cp_commit();
        cp_async16((uint32_t)__cvta_generic_to_shared(&Xs[1][xr][xc]), xbase + 32);
        cp_async16((uint32_t)__cvta_generic_to_shared(&Xs[1][xr][xc + 4]), xbase + 36);
        cp_async16((uint32_t)__cvta_generic_to_shared(&Ws[1][wr][wc]), wbase + (size_t)32 * NOUT);
        cp_commit();
    }

    float acc[2][4] = {};   // [mt][regs]

    for (int c = 0; c < NC; ++c) {
        const int cb = c % 3;

        cp_wait<1>();        // chunk c's group complete (groups retire in order)
        __syncthreads();     // visibility of all threads' copies + frees buf (c-1)%3

        // ---- issue chunk c+2 into buf (c+2)%3 == (c-1)%3 (freed by the sync above)
        if (c + 2 < NC) {
            const int nb = (c + 2) % 3;
            size_t kof = (size_t)(c + 2) * 32;
            cp_async16((uint32_t)__cvta_generic_to_shared(&Xs[nb][xr][xc]), xbase + kof);
            cp_async16((uint32_t)__cvta_generic_to_shared(&Xs[nb][xr][xc + 4]), xbase + kof + 4);
            cp_async16((uint32_t)__cvta_generic_to_shared(&Ws[nb][wr][wc]), wbase + kof * NOUT);
        }
        cp_commit();         // always commit (possibly empty) to keep group counting uniform

        // ---- compute chunk c: 4 k8-steps, warp tile m32 x n8
        #pragma unroll
        for (int ks = 0; ks < 32; ks += 8) {
            uint32_t ah[2][4];
            #pragma unroll
            for (int mt = 0; mt < 2; ++mt) {
                int ar = (wm << 5) + (mt << 4) + (lane >> 2);
                int ac = ks + (lane & 3);
                ah[mt][0] = f2tf32(Xs[cb][ar][ac]);
                ah[mt][1] = f2tf32(Xs[cb][ar + 8][ac]);
                ah[mt][2] = f2tf32(Xs[cb][ar][ac + 4]);
                ah[mt][3] = f2tf32(Xs[cb][ar + 8][ac + 4]);
            }
            const int bk = ks + (lane & 3);
            const int bn = (wn << 3) + (lane >> 2);
            uint32_t bh0 = f2tf32(Ws[cb][bk][bn]);
            uint32_t bh1 = f2tf32(Ws[cb][bk + 4][bn]);
            mma_tf32(acc[0], ah[0], bh0, bh1);
            mma_tf32(acc[1], ah[1], bh0, bh1);
        }
    }

    // ---- epilogue
    #pragma unroll
    for (int mt = 0; mt < 2; ++mt) {
        const int r0 = m0 + (wm << 5) + (mt << 4) + (lane >> 2);
        const int r1 = r0 + 8;
        const int col = n0 + (wn << 3) + ((lane & 3) << 1);
        if (MODE == 0) {
            *(float2*)(g_rs + (size_t)r0 * NOUT + col) =
                make_float2(acc[mt][0] + bias[col], acc[mt][1] + bias[col + 1]);
            *(float2*)(g_rs + (size_t)r1 * NOUT + col) =
                make_float2(acc[mt][2] + bias[col], acc[mt][3] + bias[col + 1]);
        } else {
            float den0 = g_denom[r0];
            float den1 = g_denom[r1];
            float bx0 = bias[col], bx1 = bias[col + 1];
            float2 o0, o1;
            if (den0 > 0.0f) {
                float inv0 = 1.0f / den0;
                o0 = make_float2(acc[mt][0] * inv0 + bx0, acc[mt][1] * inv0 + bx1);
            } else o0 = make_float2(boext[col], boext[col + 1]);
            if (den1 > 0.0f) {
                float inv1 = 1.0f / den1;
                o1 = make_float2(acc[mt][2] * inv1 + bx0, acc[mt][3] * inv1 + bx1);
            } else o1 = make_float2(boext[col], boext[col + 1]);
            *(float2*)(Cext + (size_t)r0 * NOUT + col) = o0;
            *(float2*)(Cext + (size_t)r1 * NOUT + col) = o1;
        }
    }
}

// ---------------- fused main pass (frozen: at the HBM ceiling) -----------------
__device__ __forceinline__ void seg_flush(int b, int lane, float4 a0, float4 a1, float dacc) {
    float* up = g_u + (size_t)b * Hh;
    atomicAdd(up + lane * 4 + 0, a0.x);
    atomicAdd(up + lane * 4 + 1, a0.y);
    atomicAdd(up + lane * 4 + 2, a0.z);
    atomicAdd(up + lane * 4 + 3, a0.w);
    atomicAdd(up + 128 + lane * 4 + 0, a1.x);
    atomicAdd(up + 128 + lane * 4 + 1, a1.y);
    atomicAdd(up + 128 + lane * 4 + 2, a1.z);
    atomicAdd(up + 128 + lane * 4 + 3, a1.w);
    if (lane == 0) atomicAdd(&g_denom[b], dacc);
}

__device__ __forceinline__ float dot8(float4 k0, float4 k1, float4 r0, float4 r1) {
    return k0.x * r0.x + k0.y * r0.y + k0.z * r0.z + k0.w * r0.w
         + k1.x * r1.x + k1.y * r1.y + k1.z * r1.z + k1.w * r1.w;
}

__global__ __launch_bounds__(256, 3) void fused_attn(const float* __restrict__ key,
                                                     const float* __restrict__ value,
                                                     const int* __restrict__ batch) {
    const int wid = (blockIdx.x * blockDim.x + threadIdx.x) >> 5;
    const int lane = threadIdx.x & 31;
    const int n0 = wid * 64;
    if (n0 >= Nn) return;

    const float4* __restrict__ key4 = (const float4*)key;
    const float4* __restrict__ val4 = (const float4*)value;
    const float4* __restrict__ rs4 = (const float4*)g_rs;

    int cur = batch[n0] & (Bq - 1);
    float4 r0 = rs4[cur * 64 + lane];
    float4 r1 = rs4[cur * 64 + 32 + lane];

    float4 a0 = make_float4(0.f, 0.f, 0.f, 0.f);
    float4 a1 = make_float4(0.f, 0.f, 0.f, 0.f);
    float dacc = 0.0f;

    float4 ka0 = key4[(size_t)n0 * 64 + lane];
    float4 ka1 = key4[(size_t)n0 * 64 + 32 + lane];
    float4 kb0 = key4[(size_t)(n0 + 1) * 64 + lane];
    float4 kb1 = key4[(size_t)(n0 + 1) * 64 + 32 + lane];

    const int n_end = n0 + 64;
    for (int n = n0; n < n_end; n += 2) {
        int2 bb = *(const int2*)(batch + n);
        int b0 = bb.x & (Bq - 1);
        int b1 = bb.y & (Bq - 1);
        int np = n + 2 < Nn ? n + 2 : Nn - 2;

        if (b0 == cur && b1 == cur) {
            float pA = dot8(ka0, ka1, r0, r1);
            float pB = dot8(kb0, kb1, r0, r1);

            ka0 = key4[(size_t)np * 64 + lane];
            ka1 = key4[(size_t)np * 64 + 32 + lane];
            kb0 = key4[(size_t)(np + 1) * 64 + lane];
            kb1 = key4[(size_t)(np + 1) * 64 + 32 + lane];

            float4 va0 = val4[(size_t)n * 64 + lane];
            float4 va1 = val4[(size_t)n * 64 + 32 + lane];
            float4 vb0 = val4[(size_t)(n + 1) * 64 + lane];
            float4 vb1 = val4[(size_t)(n + 1) * 64 + 32 + lane];

            #pragma unroll
            for (int off = 16; off; off >>= 1) {
                pA += __shfl_xor_sync(0xffffffffu, pA, off);
                pB += __shfl_xor_sync(0xffffffffu, pB, off);
            }
            float eA = __expf(pA);
            float eB = __expf(pB);
            a0.x += eA * va0.x + eB * vb0.x; a0.y += eA * va0.y + eB * vb0.y;
            a0.z += eA * va0.z + eB * vb0.z; a0.w += eA * va0.w + eB * vb0.w;
            a1.x += eA * va1.x + eB * vb1.x; a1.y += eA * va1.y + eB * vb1.y;
            a1.z += eA * va1.z + eB * vb1.z; a1.w += eA * va1.w + eB * vb1.w;
            dacc += eA + eB;
        } else {
            float4 va0 = val4[(size_t)n * 64 + lane];
            float4 va1 = val4[(size_t)n * 64 + 32 + lane];
            float4 vb0 = val4[(size_t)(n + 1) * 64 + lane];
            float4 vb1 = val4[(size_t)(n + 1) * 64 + 32 + lane];

            if (b0 != cur) {
                seg_flush(cur, lane, a0, a1, dacc);
                a0 = make_float4(0.f, 0.f, 0.f, 0.f);
                a1 = make_float4(0.f, 0.f, 0.f, 0.f);
                dacc = 0.0f;
                cur = b0;
                r0 = rs4[cur * 64 + lane];
                r1 = rs4[cur * 64 + 32 + lane];
            }
            float pA = dot8(ka0, ka1, r0, r1);
            #pragma unroll
            for (int off = 16; off; off >>= 1) pA += __shfl_xor_sync(0xffffffffu, pA, off);
            float eA = __expf(pA);
            a0.x += eA * va0.x; a0.y += eA * va0.y; a0.z += eA * va0.z; a0.w += eA * va0.w;
            a1.x += eA * va1.x; a1.y += eA * va1.y; a1.z += eA * va1.z; a1.w += eA * va1.w;
            dacc += eA;

            if (b1 != cur) {
                seg_flush(cur, lane, a0, a1, dacc);
                a0 = make_float4(0.f, 0.f, 0.f, 0.f);
                a1 = make_float4(0.f, 0.f, 0.f, 0.f);
                dacc = 0.0f;
                cur = b1;
                r0 = rs4[cur * 64 + lane];
                r1 = rs4[cur * 64 + 32 + lane];
            }
            float pB = dot8(kb0, kb1, r0, r1);
            #pragma unroll
            for (int off = 16; off; off >>= 1) pB += __shfl_xor_sync(0xffffffffu, pB, off);
            float eB = __expf(pB);
            a0.x += eB * vb0.x; a0.y += eB * vb0.y; a0.z += eB * vb0.z; a0.w += eB * vb0.w;
            a1.x += eB * vb1.x; a1.y += eB * vb1.y; a1.z += eB * vb1.z; a1.w += eB * vb1.w;
            dacc += eB;

            ka0 = key4[(size_t)np * 64 + lane];
            ka1 = key4[(size_t)np * 64 + 32 + lane];
            kb0 = key4[(size_t)(np + 1) * 64 + lane];
            kb1 = key4[(size_t)(np + 1) * 64 + 32 + lane];
        }
    }
    seg_flush(cur, lane, a0, a1, dacc);
}

// ---------------- launch ------------------------------------------------------
extern "C" void kernel_launch(void* const* d_in, const int* in_sizes, int n_in,
                              void* d_out, int out_size) {
    const float* query = (const float*)d_in[0];
    const float* key = (const float*)d_in[1];
    const float* value = (const float*)d_in[2];
    const int* batch = (const int*)d_in[3];
    const float* Wq = (const float*)d_in[4];
    const float* bq = (const float*)d_in[5];
    const float* Wk = (const float*)d_in[6];
    const float* bk = (const float*)d_in[7];
    const float* Wv = (const float*)d_in[8];
    const float* bv = (const float*)d_in[9];
    const float* Wo = (const float*)d_in[10];
    const float* bo = (const float*)d_in[11];
    float* out = (float*)d_out;

    prep_all<<<KDd + 1 + Hh + 1, 256>>>(Wq, bq, Wk, bk, Wv, bv, Wo, bo);     // 386 blocks
    gemm_tc<0><<<dim3(Hh / 32, Bq / 64), 256>>>(query, nullptr, nullptr);    // (8,128)=1024 blocks
    fused_attn<<<Nn / 64 / 8, 256>>>(key, value, batch);                     // 1024 blocks
    gemm_tc<1><<<dim3(VDd / 32, Bq / 64), 256>>>(nullptr, out, bo);          // (4,128)=512 blocks
}

// round 14
// speedup vs baseline: 1.0283x; 1.0283x over previous
#include <cuda_runtime.h>
#include <cstdint>

#define Bq 8192
#define Nn 524288
#define Hh 256
#define KDd 128
#define VDd 128
#define SCALE 0.08838834764831845f  /* 1/sqrt(128) */

#define CHUNK 32
#define NCHUNK (Nn / CHUNK)          /* 16384 */
#define PGRID 456                    /* 152 SMs x 3 resident blocks */
#define TWARPS (PGRID * 8)           /* 3648 */

// ---------------- scratch (device globals; no allocation allowed) -----------
__device__ __align__(16) float g_rs[Bq * Hh];
__device__ __align__(16) float g_u[Bq * Hh];
__device__ __align__(16) float g_denom[Bq];
__device__ __align__(16) float g_AT[KDd * Hh];    // [128][256]
__device__ __align__(16) float g_a0[Hh];
__device__ __align__(16) float g_Mt[Hh * VDd];    // [256][128]
__device__ __align__(16) float g_d[VDd];

// ---------------- merged prep (standalone; R9-proven) --------------------------
__global__ void prep_all(const float* __restrict__ Wq, const float* __restrict__ bq,
                         const float* __restrict__ Wk, const float* __restrict__ bk,
                         const float* __restrict__ Wv, const float* __restrict__ bv,
                         const float* __restrict__ Wo, const float* __restrict__ bo) {
    __shared__ float col[Hh];
    int blk = blockIdx.x;
    int t = threadIdx.x;  // 256 threads
    if (blk < KDd + 1) {
        int bi = blk;
        if (t < KDd) col[t] = (bi < KDd) ? Wq[t * KDd + bi] : bq[t];
        __syncthreads();
        float s = 0.0f;
        #pragma unroll 8
        for (int r = 0; r < KDd; ++r) s += Wk[r * Hh + t] * col[r];
        if (bi < KDd) g_AT[bi * Hh + t] = s * SCALE;
        else          g_a0[t] = s * SCALE;
    } else {
        int j = blk - (KDd + 1);   // 0..256
        if (t < VDd) col[t] = (j < Hh) ? Wv[t * Hh + j] : bv[t];
        __syncthreads();
        if (t < VDd) {
            float acc = 0.0f;
            const float4* wrow = (const float4*)(Wo + t * VDd);
            #pragma unroll 8
            for (int o4 = 0; o4 < VDd / 4; ++o4) {
                float4 w = wrow[o4];
                int o = o4 * 4;
                acc += w.x * col[o] + w.y * col[o + 1] + w.z * col[o + 2] + w.w * col[o + 3];
            }
            if (j < Hh) g_Mt[j * VDd + t] = acc;
            else        g_d[t] = acc + bo[t];
        }
    }
}

// ---------------- tf32 / cp.async helpers --------------------------------------
__device__ __forceinline__ uint32_t f2tf32(float x) {
    uint32_t r;
    asm("cvt.rna.tf32.f32 %0, %1;" : "=r"(r) : "f"(x));
    return r;
}

__device__ __forceinline__ void mma_tf32(float* c, const uint32_t* a, uint32_t b0, uint32_t b1) {
    asm volatile(
        "mma.sync.aligned.m16n8k8.row.col.f32.tf32.tf32.f32 "
        "{%0,%1,%2,%3}, {%4,%5,%6,%7}, {%8,%9}, {%0,%1,%2,%3};"
        : "+f"(c[0]), "+f"(c[1]), "+f"(c[2]), "+f"(c[3])
        : "r"(a[0]), "r"(a[1]), "r"(a[2]), "r"(a[3]), "r"(b0), "r"(b1));
}

__device__ __forceinline__ void cp_async16(uint32_t smem_dst, const void* gmem_src) {
    asm volatile("cp.async.cg.shared.global [%0], [%1], 16;\n" :: "r"(smem_dst), "l"(gmem_src));
}
__device__ __forceinline__ void cp_commit() {
    asm volatile("cp.async.commit_group;\n" ::: "memory");
}
template <int N>
__device__ __forceinline__ void cp_wait() {
    asm volatile("cp.async.wait_group %0;\n" :: "n"(N) : "memory");
}

// ---------------- tf32 GEMM: 3-stage cp.async pipeline (R13; at its floor) -----
// MODE 0: g_rs = query @ g_AT + g_a0    K=128, NC=4, grid (8,128)=1024. + zero g_u.
// MODE 1: out = (g_u/den) @ g_Mt + g_d  K=256, NC=8, grid (4,128)=512.
template <int MODE>
__global__ __launch_bounds__(256) void gemm_tc(const float* __restrict__ Xext,
                                               float* __restrict__ Cext,
                                               const float* __restrict__ boext) {
    constexpr int K = (MODE == 0) ? KDd : Hh;
    constexpr int NOUT = (MODE == 0) ? Hh : VDd;
    constexpr int NC = K / 32;
    const float* X = (MODE == 0) ? Xext : g_u;
    const float* W = (MODE == 0) ? g_AT : g_Mt;
    const float* bias = (MODE == 0) ? g_a0 : g_d;

    const int tid = threadIdx.x;
    const int warp = tid >> 5;
    const int lane = tid & 31;
    const int wm = warp & 1;
    const int wn = warp >> 1;

    if (MODE == 0) {
        int bid = blockIdx.y * gridDim.x + blockIdx.x;  // 0..1023
        float4 z = make_float4(0.f, 0.f, 0.f, 0.f);
        float4* u4 = (float4*)g_u;
        u4[(size_t)bid * 512 + tid] = z;
        u4[(size_t)bid * 512 + 256 + tid] = z;
        if (tid < 8) g_denom[bid * 8 + tid] = 0.0f;
    }

    __shared__ float Xs[3][64][36];
    __shared__ float Ws[3][32][40];

    const int m0 = blockIdx.y * 64;
    const int n0 = blockIdx.x * 32;

    const int xr = tid >> 2;
    const int xc = (tid & 3) << 3;
    const int wr = tid >> 3;
    const int wc = (tid & 7) << 2;

    const float* xbase = X + (size_t)(m0 + xr) * K + xc;
    const float* wbase = W + (size_t)wr * NOUT + n0 + wc;

    {
        cp_async16((uint32_t)__cvta_generic_to_shared(&Xs[0][xr][xc]), xbase);
        cp_async16((uint32_t)__cvta_generic_to_shared(&Xs[0][xr][xc + 4]), xbase + 4);
        cp_async16((uint32_t)__cvta_generic_to_shared(&Ws[0][wr][wc]), wbase);
        cp_commit();
        cp_async16((uint32_t)__cvta_generic_to_shared(&Xs[1][xr][xc]), xbase + 32);
        cp_async16((uint32_t)__cvta_generic_to_shared(&Xs[1][xr][xc + 4]), xbase + 36);
        cp_async16((uint32_t)__cvta_generic_to_shared(&Ws[1][wr][wc]), wbase + (size_t)32 * NOUT);
        cp_commit();
    }

    float acc[2][4] = {};

    for (int c = 0; c < NC; ++c) {
        const int cb = c % 3;

        cp_wait<1>();
        __syncthreads();

        if (c + 2 < NC) {
            const int nb = (c + 2) % 3;
            size_t kof = (size_t)(c + 2) * 32;
            cp_async16((uint32_t)__cvta_generic_to_shared(&Xs[nb][xr][xc]), xbase + kof);
            cp_async16((uint32_t)__cvta_generic_to_shared(&Xs[nb][xr][xc + 4]), xbase + kof + 4);
            cp_async16((uint32_t)__cvta_generic_to_shared(&Ws[nb][wr][wc]), wbase + kof * NOUT);
        }
        cp_commit();

        #pragma unroll
        for (int ks = 0; ks < 32; ks += 8) {
            uint32_t ah[2][4];
            #pragma unroll
            for (int mt = 0; mt < 2; ++mt) {
                int ar = (wm << 5) + (mt << 4) + (lane >> 2);
                int ac = ks + (lane & 3);
                ah[mt][0] = f2tf32(Xs[cb][ar][ac]);
                ah[mt][1] = f2tf32(Xs[cb][ar + 8][ac]);
                ah[mt][2] = f2tf32(Xs[cb][ar][ac + 4]);
                ah[mt][3] = f2tf32(Xs[cb][ar + 8][ac + 4]);
            }
            const int bk = ks + (lane & 3);
            const int bn = (wn << 3) + (lane >> 2);
            uint32_t bh0 = f2tf32(Ws[cb][bk][bn]);
            uint32_t bh1 = f2tf32(Ws[cb][bk + 4][bn]);
            mma_tf32(acc[0], ah[0], bh0, bh1);
            mma_tf32(acc[1], ah[1], bh0, bh1);
        }
    }

    #pragma unroll
    for (int mt = 0; mt < 2; ++mt) {
        const int r0 = m0 + (wm << 5) + (mt << 4) + (lane >> 2);
        const int r1 = r0 + 8;
        const int col = n0 + (wn << 3) + ((lane & 3) << 1);
        if (MODE == 0) {
            *(float2*)(g_rs + (size_t)r0 * NOUT + col) =
                make_float2(acc[mt][0] + bias[col], acc[mt][1] + bias[col + 1]);
            *(float2*)(g_rs + (size_t)r1 * NOUT + col) =
                make_float2(acc[mt][2] + bias[col], acc[mt][3] + bias[col + 1]);
        } else {
            float den0 = g_denom[r0];
            float den1 = g_denom[r1];
            float bx0 = bias[col], bx1 = bias[col + 1];
            float2 o0, o1;
            if (den0 > 0.0f) {
                float inv0 = 1.0f / den0;
                o0 = make_float2(acc[mt][0] * inv0 + bx0, acc[mt][1] * inv0 + bx1);
            } else o0 = make_float2(boext[col], boext[col + 1]);
            if (den1 > 0.0f) {
                float inv1 = 1.0f / den1;
                o1 = make_float2(acc[mt][2] * inv1 + bx0, acc[mt][3] * inv1 + bx1);
            } else o1 = make_float2(boext[col], boext[col + 1]);
            *(float2*)(Cext + (size_t)r0 * NOUT + col) = o0;
            *(float2*)(Cext + (size_t)r1 * NOUT + col) = o1;
        }
    }
}

// ---------------- fused main pass: persistent-strided 32-node chunks -----------
__device__ __forceinline__ void seg_flush(int b, int lane, float4 a0, float4 a1, float dacc) {
    float* up = g_u + (size_t)b * Hh;
    atomicAdd(up + lane * 4 + 0, a0.x);
    atomicAdd(up + lane * 4 + 1, a0.y);
    atomicAdd(up + lane * 4 + 2, a0.z);
    atomicAdd(up + lane * 4 + 3, a0.w);
    atomicAdd(up + 128 + lane * 4 + 0, a1.x);
    atomicAdd(up + 128 + lane * 4 + 1, a1.y);
    atomicAdd(up + 128 + lane * 4 + 2, a1.z);
    atomicAdd(up + 128 + lane * 4 + 3, a1.w);
    if (lane == 0) atomicAdd(&g_denom[b], dacc);
}

__device__ __forceinline__ float dot8(float4 k0, float4 k1, float4 r0, float4 r1) {
    return k0.x * r0.x + k0.y * r0.y + k0.z * r0.z + k0.w * r0.w
         + k1.x * r1.x + k1.y * r1.y + k1.z * r1.z + k1.w * r1.w;
}

// Grid = 456 blocks (3 resident/SM on 152 SMs); each warp loops 32-node chunks
// strided by TWARPS. Equalizes per-SM work to a 32-node quantum (kills the
// 0.25-wave tail of the old 1024-block launch). Inner loop identical to the
// frozen R12 form; key prefetch clamped within-chunk (boundary reload = L1 hit).
__global__ __launch_bounds__(256, 3) void fused_attn(const float* __restrict__ key,
                                                     const float* __restrict__ value,
                                                     const int* __restrict__ batch) {
    const int gwid = (blockIdx.x * blockDim.x + threadIdx.x) >> 5;
    const int lane = threadIdx.x & 31;

    const float4* __restrict__ key4 = (const float4*)key;
    const float4* __restrict__ val4 = (const float4*)value;
    const float4* __restrict__ rs4 = (const float4*)g_rs;

    for (int chunk = gwid; chunk < NCHUNK; chunk += TWARPS) {
        const int n0 = chunk * CHUNK;
        const int n_end = n0 + CHUNK;

        int cur = batch[n0] & (Bq - 1);
        float4 r0 = rs4[cur * 64 + lane];
        float4 r1 = rs4[cur * 64 + 32 + lane];

        float4 a0 = make_float4(0.f, 0.f, 0.f, 0.f);
        float4 a1 = make_float4(0.f, 0.f, 0.f, 0.f);
        float dacc = 0.0f;

        float4 ka0 = key4[(size_t)n0 * 64 + lane];
        float4 ka1 = key4[(size_t)n0 * 64 + 32 + lane];
        float4 kb0 = key4[(size_t)(n0 + 1) * 64 + lane];
        float4 kb1 = key4[(size_t)(n0 + 1) * 64 + 32 + lane];

        for (int n = n0; n < n_end; n += 2) {
            int2 bb = *(const int2*)(batch + n);
            int b0 = bb.x & (Bq - 1);
            int b1 = bb.y & (Bq - 1);
            int np = (n + 2 < n_end) ? n + 2 : n;   // clamp inside chunk (reload = L1 hit)

            if (b0 == cur && b1 == cur) {
                float pA = dot8(ka0, ka1, r0, r1);
                float pB = dot8(kb0, kb1, r0, r1);

                ka0 = key4[(size_t)np * 64 + lane];
                ka1 = key4[(size_t)np * 64 + 32 + lane];
                kb0 = key4[(size_t)(np + 1) * 64 + lane];
                kb1 = key4[(size_t)(np + 1) * 64 + 32 + lane];

                float4 va0 = val4[(size_t)n * 64 + lane];
                float4 va1 = val4[(size_t)n * 64 + 32 + lane];
                float4 vb0 = val4[(size_t)(n + 1) * 64 + lane];
                float4 vb1 = val4[(size_t)(n + 1) * 64 + 32 + lane];

                #pragma unroll
                for (int off = 16; off; off >>= 1) {
                    pA += __shfl_xor_sync(0xffffffffu, pA, off);
                    pB += __shfl_xor_sync(0xffffffffu, pB, off);
                }
                float eA = __expf(pA);
                float eB = __expf(pB);
                a0.x += eA * va0.x + eB * vb0.x; a0.y += eA * va0.y + eB * vb0.y;
                a0.z += eA * va0.z + eB * vb0.z; a0.w += eA * va0.w + eB * vb0.w;
                a1.x += eA * va1.x + eB * vb1.x; a1.y += eA * va1.y + eB * vb1.y;
                a1.z += eA * va1.z + eB * vb1.z; a1.w += eA * va1.w + eB * vb1.w;
                dacc += eA + eB;
            } else {
                float4 va0 = val4[(size_t)n * 64 + lane];
                float4 va1 = val4[(size_t)n * 64 + 32 + lane];
                float4 vb0 = val4[(size_t)(n + 1) * 64 + lane];
                float4 vb1 = val4[(size_t)(n + 1) * 64 + 32 + lane];

                if (b0 != cur) {
                    seg_flush(cur, lane, a0, a1, dacc);
                    a0 = make_float4(0.f, 0.f, 0.f, 0.f);
                    a1 = make_float4(0.f, 0.f, 0.f, 0.f);
                    dacc = 0.0f;
                    cur = b0;
                    r0 = rs4[cur * 64 + lane];
                    r1 = rs4[cur * 64 + 32 + lane];
                }
                float pA = dot8(ka0, ka1, r0, r1);
                #pragma unroll
                for (int off = 16; off; off >>= 1) pA += __shfl_xor_sync(0xffffffffu, pA, off);
                float eA = __expf(pA);
                a0.x += eA * va0.x; a0.y += eA * va0.y; a0.z += eA * va0.z; a0.w += eA * va0.w;
                a1.x += eA * va1.x; a1.y += eA * va1.y; a1.z += eA * va1.z; a1.w += eA * va1.w;
                dacc += eA;

                if (b1 != cur) {
                    seg_flush(cur, lane, a0, a1, dacc);
                    a0 = make_float4(0.f, 0.f, 0.f, 0.f);
                    a1 = make_float4(0.f, 0.f, 0.f, 0.f);
                    dacc = 0.0f;
                    cur = b1;
                    r0 = rs4[cur * 64 + lane];
                    r1 = rs4[cur * 64 + 32 + lane];
                }
                float pB = dot8(kb0, kb1, r0, r1);
                #pragma unroll
                for (int off = 16; off; off >>= 1) pB += __shfl_xor_sync(0xffffffffu, pB, off);
                float eB = __expf(pB);
                a0.x += eB * vb0.x; a0.y += eB * vb0.y; a0.z += eB * vb0.z; a0.w += eB * vb0.w;
                a1.x += eB * vb1.x; a1.y += eB * vb1.y; a1.z += eB * vb1.z; a1.w += eB * vb1.w;
                dacc += eB;

                ka0 = key4[(size_t)np * 64 + lane];
                ka1 = key4[(size_t)np * 64 + 32 + lane];
                kb0 = key4[(size_t)(np + 1) * 64 + lane];
                kb1 = key4[(size_t)(np + 1) * 64 + 32 + lane];
            }
        }
        seg_flush(cur, lane, a0, a1, dacc);
    }
}

// ---------------- launch ------------------------------------------------------
extern "C" void kernel_launch(void* const* d_in, const int* in_sizes, int n_in,
                              void* d_out, int out_size) {
    const float* query = (const float*)d_in[0];
    const float* key = (const float*)d_in[1];
    const float* value = (const float*)d_in[2];
    const int* batch = (const int*)d_in[3];
    const float* Wq = (const float*)d_in[4];
    const float* bq = (const float*)d_in[5];
    const float* Wk = (const float*)d_in[6];
    const float* bk = (const float*)d_in[7];
    const float* Wv = (const float*)d_in[8];
    const float* bv = (const float*)d_in[9];
    const float* Wo = (const float*)d_in[10];
    const float* bo = (const float*)d_in[11];
    float* out = (float*)d_out;

    prep_all<<<KDd + 1 + Hh + 1, 256>>>(Wq, bq, Wk, bk, Wv, bv, Wo, bo);     // 386 blocks
    gemm_tc<0><<<dim3(Hh / 32, Bq / 64), 256>>>(query, nullptr, nullptr);    // (8,128)=1024 blocks
    fused_attn<<<PGRID, 256>>>(key, value, batch);                           // 456 persistent blocks
    gemm_tc<1><<<dim3(VDd / 32, Bq / 64), 256>>>(nullptr, out, bo);          // (4,128)=512 blocks
}

// round 15
// speedup vs baseline: 1.0741x; 1.0445x over previous
#include <cuda_runtime.h>
#include <cstdint>

#define Bq 8192
#define Nn 524288
#define Hh 256
#define KDd 128
#define VDd 128
#define SCALE 0.08838834764831845f  /* 1/sqrt(128) */

#define CHUNK 32
#define NCHUNK (Nn / CHUNK)          /* 16384 */
#define PGRID 456                    /* 152 SMs x 3 resident blocks */
#define TWARPS (PGRID * 8)           /* 3648 */

// ---------------- scratch (device globals; no allocation allowed) -----------
__device__ __align__(16) float g_rs[Bq * Hh];
__device__ __align__(16) float g_u[Bq * Hh];
__device__ __align__(16) float g_denom[Bq];
__device__ __align__(16) float g_AT[KDd * Hh];    // [128][256]
__device__ __align__(16) float g_a0[Hh];
__device__ __align__(16) float g_Mt[Hh * VDd];    // [256][128]
__device__ __align__(16) float g_d[VDd];

// ---------------- merged prep + g_u/g_denom zero-init --------------------------
__global__ void prep_all(const float* __restrict__ Wq, const float* __restrict__ bq,
                         const float* __restrict__ Wk, const float* __restrict__ bk,
                         const float* __restrict__ Wv, const float* __restrict__ bv,
                         const float* __restrict__ Wo, const float* __restrict__ bo) {
    __shared__ float col[Hh];
    int blk = blockIdx.x;
    int t = threadIdx.x;  // 256 threads

    // grid-strided zero of g_u (2M float4) and g_denom — overlaps the compute below
    {
        float4 z = make_float4(0.f, 0.f, 0.f, 0.f);
        float4* u4 = (float4*)g_u;
        for (int i = blk * 256 + t; i < Bq * Hh / 4; i += (KDd + 1 + Hh + 1) * 256)
            u4[i] = z;
        for (int i = blk * 256 + t; i < Bq; i += (KDd + 1 + Hh + 1) * 256)
            g_denom[i] = 0.0f;
    }

    if (blk < KDd + 1) {
        int bi = blk;
        if (t < KDd) col[t] = (bi < KDd) ? Wq[t * KDd + bi] : bq[t];
        __syncthreads();
        float s = 0.0f;
        #pragma unroll 8
        for (int r = 0; r < KDd; ++r) s += Wk[r * Hh + t] * col[r];
        if (bi < KDd) g_AT[bi * Hh + t] = s * SCALE;
        else          g_a0[t] = s * SCALE;
    } else {
        int j = blk - (KDd + 1);   // 0..256
        if (t < VDd) col[t] = (j < Hh) ? Wv[t * Hh + j] : bv[t];
        __syncthreads();
        if (t < VDd) {
            float acc = 0.0f;
            const float4* wrow = (const float4*)(Wo + t * VDd);
            #pragma unroll 8
            for (int o4 = 0; o4 < VDd / 4; ++o4) {
                float4 w = wrow[o4];
                int o = o4 * 4;
                acc += w.x * col[o] + w.y * col[o + 1] + w.z * col[o + 2] + w.w * col[o + 3];
            }
            if (j < Hh) g_Mt[j * VDd + t] = acc;
            else        g_d[t] = acc + bo[t];
        }
    }
}

// ---------------- tf32 / cp.async helpers --------------------------------------
__device__ __forceinline__ uint32_t f2tf32(float x) {
    uint32_t r;
    asm("cvt.rna.tf32.f32 %0, %1;" : "=r"(r) : "f"(x));
    return r;
}

__device__ __forceinline__ void mma_tf32(float* c, const uint32_t* a, uint32_t b0, uint32_t b1) {
    asm volatile(
        "mma.sync.aligned.m16n8k8.row.col.f32.tf32.tf32.f32 "
        "{%0,%1,%2,%3}, {%4,%5,%6,%7}, {%8,%9}, {%0,%1,%2,%3};"
        : "+f"(c[0]), "+f"(c[1]), "+f"(c[2]), "+f"(c[3])
        : "r"(a[0]), "r"(a[1]), "r"(a[2]), "r"(a[3]), "r"(b0), "r"(b1));
}

__device__ __forceinline__ void cp_async16(uint32_t smem_dst, const void* gmem_src) {
    asm volatile("cp.async.cg.shared.global [%0], [%1], 16;\n" :: "r"(smem_dst), "l"(gmem_src));
}
__device__ __forceinline__ void cp_commit() {
    asm volatile("cp.async.commit_group;\n" ::: "memory");
}
template <int N>
__device__ __forceinline__ void cp_wait() {
    asm volatile("cp.async.wait_group %0;\n" :: "n"(N) : "memory");
}

// ---------------- tf32 GEMM: 3-stage cp.async pipeline (R13 form) --------------
// MODE 0: g_rs = query @ g_AT + g_a0    K=128, NC=4, grid (8,128)=1024.
// MODE 1: out = (g_u/den) @ g_Mt + g_d  K=256, NC=8, grid (4,128)=512.
template <int MODE>
__global__ __launch_bounds__(256) void gemm_tc(const float* __restrict__ Xext,
                                               float* __restrict__ Cext,
                                               const float* __restrict__ boext) {
    constexpr int K = (MODE == 0) ? KDd : Hh;
    constexpr int NOUT = (MODE == 0) ? Hh : VDd;
    constexpr int NC = K / 32;
    const float* X = (MODE == 0) ? Xext : g_u;
    const float* W = (MODE == 0) ? g_AT : g_Mt;
    const float* bias = (MODE == 0) ? g_a0 : g_d;

    const int tid = threadIdx.x;
    const int warp = tid >> 5;
    const int lane = tid & 31;
    const int wm = warp & 1;
    const int wn = warp >> 1;

    __shared__ float Xs[3][64][36];
    __shared__ float Ws[3][32][40];

    const int m0 = blockIdx.y * 64;
    const int n0 = blockIdx.x * 32;

    const int xr = tid >> 2;
    const int xc = (tid & 3) << 3;
    const int wr = tid >> 3;
    const int wc = (tid & 7) << 2;

    const float* xbase = X + (size_t)(m0 + xr) * K + xc;
    const float* wbase = W + (size_t)wr * NOUT + n0 + wc;

    {
        cp_async16((uint32_t)__cvta_generic_to_shared(&Xs[0][xr][xc]), xbase);
        cp_async16((uint32_t)__cvta_generic_to_shared(&Xs[0][xr][xc + 4]), xbase + 4);
        cp_async16((uint32_t)__cvta_generic_to_shared(&Ws[0][wr][wc]), wbase);
        cp_commit();
        cp_async16((uint32_t)__cvta_generic_to_shared(&Xs[1][xr][xc]), xbase + 32);
        cp_async16((uint32_t)__cvta_generic_to_shared(&Xs[1][xr][xc + 4]), xbase + 36);
        cp_async16((uint32_t)__cvta_generic_to_shared(&Ws[1][wr][wc]), wbase + (size_t)32 * NOUT);
        cp_commit();
    }

    float acc[2][4] = {};

    for (int c = 0; c < NC; ++c) {
        const int cb = c % 3;

        cp_wait<1>();
        __syncthreads();

        if (c + 2 < NC) {
            const int nb = (c + 2) % 3;
            size_t kof = (size_t)(c + 2) * 32;
            cp_async16((uint32_t)__cvta_generic_to_shared(&Xs[nb][xr][xc]), xbase + kof);
            cp_async16((uint32_t)__cvta_generic_to_shared(&Xs[nb][xr][xc + 4]), xbase + kof + 4);
            cp_async16((uint32_t)__cvta_generic_to_shared(&Ws[nb][wr][wc]), wbase + kof * NOUT);
        }
        cp_commit();

        #pragma unroll
        for (int ks = 0; ks < 32; ks += 8) {
            uint32_t ah[2][4];
            #pragma unroll
            for (int mt = 0; mt < 2; ++mt) {
                int ar = (wm << 5) + (mt << 4) + (lane >> 2);
                int ac = ks + (lane & 3);
                ah[mt][0] = f2tf32(Xs[cb][ar][ac]);
                ah[mt][1] = f2tf32(Xs[cb][ar + 8][ac]);
                ah[mt][2] = f2tf32(Xs[cb][ar][ac + 4]);
                ah[mt][3] = f2tf32(Xs[cb][ar + 8][ac + 4]);
            }
            const int bk = ks + (lane & 3);
            const int bn = (wn << 3) + (lane >> 2);
            uint32_t bh0 = f2tf32(Ws[cb][bk][bn]);
            uint32_t bh1 = f2tf32(Ws[cb][bk + 4][bn]);
            mma_tf32(acc[0], ah[0], bh0, bh1);
            mma_tf32(acc[1], ah[1], bh0, bh1);
        }
    }

    #pragma unroll
    for (int mt = 0; mt < 2; ++mt) {
        const int r0 = m0 + (wm << 5) + (mt << 4) + (lane >> 2);
        const int r1 = r0 + 8;
        const int col = n0 + (wn << 3) + ((lane & 3) << 1);
        if (MODE == 0) {
            *(float2*)(g_rs + (size_t)r0 * NOUT + col) =
                make_float2(acc[mt][0] + bias[col], acc[mt][1] + bias[col + 1]);
            *(float2*)(g_rs + (size_t)r1 * NOUT + col) =
                make_float2(acc[mt][2] + bias[col], acc[mt][3] + bias[col + 1]);
        } else {
            float den0 = g_denom[r0];
            float den1 = g_denom[r1];
            float bx0 = bias[col], bx1 = bias[col + 1];
            float2 o0, o1;
            if (den0 > 0.0f) {
                float inv0 = 1.0f / den0;
                o0 = make_float2(acc[mt][0] * inv0 + bx0, acc[mt][1] * inv0 + bx1);
            } else o0 = make_float2(boext[col], boext[col + 1]);
            if (den1 > 0.0f) {
                float inv1 = 1.0f / den1;
                o1 = make_float2(acc[mt][2] * inv1 + bx0, acc[mt][3] * inv1 + bx1);
            } else o1 = make_float2(boext[col], boext[col + 1]);
            *(float2*)(Cext + (size_t)r0 * NOUT + col) = o0;
            *(float2*)(Cext + (size_t)r1 * NOUT + col) = o1;
        }
    }
}

// ---------------- fused main pass: persistent + streaming loads ----------------
__device__ __forceinline__ void seg_flush(int b, int lane, float4 a0, float4 a1, float dacc) {
    float* up = g_u + (size_t)b * Hh;
    atomicAdd(up + lane * 4 + 0, a0.x);
    atomicAdd(up + lane * 4 + 1, a0.y);
    atomicAdd(up + lane * 4 + 2, a0.z);
    atomicAdd(up + lane * 4 + 3, a0.w);
    atomicAdd(up + 128 + lane * 4 + 0, a1.x);
    atomicAdd(up + 128 + lane * 4 + 1, a1.y);
    atomicAdd(up + 128 + lane * 4 + 2, a1.z);
    atomicAdd(up + 128 + lane * 4 + 3, a1.w);
    if (lane == 0) atomicAdd(&g_denom[b], dacc);
}

__device__ __forceinline__ float dot8(float4 k0, float4 k1, float4 r0, float4 r1) {
    return k0.x * r0.x + k0.y * r0.y + k0.z * r0.z + k0.w * r0.w
         + k1.x * r1.x + k1.y * r1.y + k1.z * r1.z + k1.w * r1.w;
}

// key/value/batch are read exactly once -> __ldcs (evict-first): the 1.07GB
// stream no longer displaces g_u/g_rs (16MB working set) from L2, so gemm_tc<1>
// reads g_u as L2 hits instead of DRAM refetches.
__global__ __launch_bounds__(256, 3) void fused_attn(const float* __restrict__ key,
                                                     const float* __restrict__ value,
                                                     const int* __restrict__ batch) {
    const int gwid = (blockIdx.x * blockDim.x + threadIdx.x) >> 5;
    const int lane = threadIdx.x & 31;

    const float4* __restrict__ key4 = (const float4*)key;
    const float4* __restrict__ val4 = (const float4*)value;
    const float4* __restrict__ rs4 = (const float4*)g_rs;

    for (int chunk = gwid; chunk < NCHUNK; chunk += TWARPS) {
        const int n0 = chunk * CHUNK;
        const int n_end = n0 + CHUNK;

        int cur = __ldcs(batch + n0) & (Bq - 1);
        float4 r0 = rs4[cur * 64 + lane];
        float4 r1 = rs4[cur * 64 + 32 + lane];

        float4 a0 = make_float4(0.f, 0.f, 0.f, 0.f);
        float4 a1 = make_float4(0.f, 0.f, 0.f, 0.f);
        float dacc = 0.0f;

        float4 ka0 = __ldcs(key4 + (size_t)n0 * 64 + lane);
        float4 ka1 = __ldcs(key4 + (size_t)n0 * 64 + 32 + lane);
        float4 kb0 = __ldcs(key4 + (size_t)(n0 + 1) * 64 + lane);
        float4 kb1 = __ldcs(key4 + (size_t)(n0 + 1) * 64 + 32 + lane);

        for (int n = n0; n < n_end; n += 2) {
            int2 bb = __ldcs((const int2*)(batch + n));
            int b0 = bb.x & (Bq - 1);
            int b1 = bb.y & (Bq - 1);
            int np = (n + 2 < n_end) ? n + 2 : n;   // clamp inside chunk

            if (b0 == cur && b1 == cur) {
                float pA = dot8(ka0, ka1, r0, r1);
                float pB = dot8(kb0, kb1, r0, r1);

                ka0 = __ldcs(key4 + (size_t)np * 64 + lane);
                ka1 = __ldcs(key4 + (size_t)np * 64 + 32 + lane);
                kb0 = __ldcs(key4 + (size_t)(np + 1) * 64 + lane);
                kb1 = __ldcs(key4 + (size_t)(np + 1) * 64 + 32 + lane);

                float4 va0 = __ldcs(val4 + (size_t)n * 64 + lane);
                float4 va1 = __ldcs(val4 + (size_t)n * 64 + 32 + lane);
                float4 vb0 = __ldcs(val4 + (size_t)(n + 1) * 64 + lane);
                float4 vb1 = __ldcs(val4 + (size_t)(n + 1) * 64 + 32 + lane);

                #pragma unroll
                for (int off = 16; off; off >>= 1) {
                    pA += __shfl_xor_sync(0xffffffffu, pA, off);
                    pB += __shfl_xor_sync(0xffffffffu, pB, off);
                }
                float eA = __expf(pA);
                float eB = __expf(pB);
                a0.x += eA * va0.x + eB * vb0.x; a0.y += eA * va0.y + eB * vb0.y;
                a0.z += eA * va0.z + eB * vb0.z; a0.w += eA * va0.w + eB * vb0.w;
                a1.x += eA * va1.x + eB * vb1.x; a1.y += eA * va1.y + eB * vb1.y;
                a1.z += eA * va1.z + eB * vb1.z; a1.w += eA * va1.w + eB * vb1.w;
                dacc += eA + eB;
            } else {
                float4 va0 = __ldcs(val4 + (size_t)n * 64 + lane);
                float4 va1 = __ldcs(val4 + (size_t)n * 64 + 32 + lane);
                float4 vb0 = __ldcs(val4 + (size_t)(n + 1) * 64 + lane);
                float4 vb1 = __ldcs(val4 + (size_t)(n + 1) * 64 + 32 + lane);

                if (b0 != cur) {
                    seg_flush(cur, lane, a0, a1, dacc);
                    a0 = make_float4(0.f, 0.f, 0.f, 0.f);
                    a1 = make_float4(0.f, 0.f, 0.f, 0.f);
                    dacc = 0.0f;
                    cur = b0;
                    r0 = rs4[cur * 64 + lane];
                    r1 = rs4[cur * 64 + 32 + lane];
                }
                float pA = dot8(ka0, ka1, r0, r1);
                #pragma unroll
                for (int off = 16; off; off >>= 1) pA += __shfl_xor_sync(0xffffffffu, pA, off);
                float eA = __expf(pA);
                a0.x += eA * va0.x; a0.y += eA * va0.y; a0.z += eA * va0.z; a0.w += eA * va0.w;
                a1.x += eA * va1.x; a1.y += eA * va1.y; a1.z += eA * va1.z; a1.w += eA * va1.w;
                dacc += eA;

                if (b1 != cur) {
                    seg_flush(cur, lane, a0, a1, dacc);
                    a0 = make_float4(0.f, 0.f, 0.f, 0.f);
                    a1 = make_float4(0.f, 0.f, 0.f, 0.f);
                    dacc = 0.0f;
                    cur = b1;
                    r0 = rs4[cur * 64 + lane];
                    r1 = rs4[cur * 64 + 32 + lane];
                }
                float pB = dot8(kb0, kb1, r0, r1);
                #pragma unroll
                for (int off = 16; off; off >>= 1) pB += __shfl_xor_sync(0xffffffffu, pB, off);
                float eB = __expf(pB);
                a0.x += eB * vb0.x; a0.y += eB * vb0.y; a0.z += eB * vb0.z; a0.w += eB * vb0.w;
                a1.x += eB * vb1.x; a1.y += eB * vb1.y; a1.z += eB * vb1.z; a1.w += eB * vb1.w;
                dacc += eB;

                ka0 = __ldcs(key4 + (size_t)np * 64 + lane);
                ka1 = __ldcs(key4 + (size_t)np * 64 + 32 + lane);
                kb0 = __ldcs(key4 + (size_t)(np + 1) * 64 + lane);
                kb1 = __ldcs(key4 + (size_t)(np + 1) * 64 + 32 + lane);
            }
        }
        seg_flush(cur, lane, a0, a1, dacc);
    }
}

// ---------------- launch ------------------------------------------------------
extern "C" void kernel_launch(void* const* d_in, const int* in_sizes, int n_in,
                              void* d_out, int out_size) {
    const float* query = (const float*)d_in[0];
    const float* key = (const float*)d_in[1];
    const float* value = (const float*)d_in[2];
    const int* batch = (const int*)d_in[3];
    const float* Wq = (const float*)d_in[4];
    const float* bq = (const float*)d_in[5];
    const float* Wk = (const float*)d_in[6];
    const float* bk = (const float*)d_in[7];
    const float* Wv = (const float*)d_in[8];
    const float* bv = (const float*)d_in[9];
    const float* Wo = (const float*)d_in[10];
    const float* bo = (const float*)d_in[11];
    float* out = (float*)d_out;

    prep_all<<<KDd + 1 + Hh + 1, 256>>>(Wq, bq, Wk, bk, Wv, bv, Wo, bo);     // 386 blocks (+ zero g_u)
    gemm_tc<0><<<dim3(Hh / 32, Bq / 64), 256>>>(query, nullptr, nullptr);    // (8,128)=1024 blocks
    fused_attn<<<PGRID, 256>>>(key, value, batch);                           // 456 persistent blocks
    gemm_tc<1><<<dim3(VDd / 32, Bq / 64), 256>>>(nullptr, out, bo);          // (4,128)=512 blocks
}